// round 14
// baseline (speedup 1.0000x reference)
#include <cuda_runtime.h>
#include <cuda_fp16.h>
#include <cstdint>

// Causal FlashAttention via fp16 mma.sync with asymmetric split (sm_103).
// S = (Qhi+Qlo)*Khi (exact-Q x fp16-K, 2 terms — protects the exponent),
// O = Phi*Vhi       (fp16-P x fp16-V, 1 term — P enters linearly, err ~3e-4).
// Warp-specialized: 8 consumer + 4 producer warps, 4-stage mbarrier ring.
// R13: Plo term dropped; O-rescale skipped when row max unchanged (warp-uniform).

#define HD 128
#define BT 128                     // q rows per CTA
#define BC 64                      // kv rows per chunk
#define STR 136                    // smem row stride in fp16 elems (272 B)
#define ROWB (STR * 2)             // 272 bytes per row
#define QTILE_B (BT * ROWB)        // 34816 B
#define CTILE_B (BC * ROWB)        // 17408 B per tile buffer
#define NSTG 4
#define SCALE_L2E 0.12753102331595943f  // (1/sqrt(128)) * log2(e)

// smem map (bytes): full[s]=s*8, empty[s]=32+s*8
#define SQHI 1024
#define SQLO (SQHI + QTILE_B)
#define STG0 (SQLO + QTILE_B)          // stage s at STG0 + s*STAGE_B
#define STAGE_B (2 * CTILE_B)          // K, V (hi only)
#define OFF_K 0
#define OFF_V CTILE_B
#define SM_TOTAL (STG0 + NSTG * STAGE_B)  // 209920 B

__device__ __forceinline__ uint32_t smem_u32(const void* p) {
    uint32_t a;
    asm("{ .reg .u64 t; cvta.to.shared.u64 t, %1; cvt.u32.u64 %0, t; }" : "=r"(a) : "l"(p));
    return a;
}

// pack two f32 -> f16x2 (lo = f0, hi = f1)
__device__ __forceinline__ uint32_t packh2(float f0, float f1) {
    uint32_t r;
    asm("cvt.rn.f16x2.f32 %0, %1, %2;" : "=r"(r) : "f"(f1), "f"(f0));
    return r;
}
// split two floats into fp16x2 hi + fp16x2 lo (lo = rounded residual)
__device__ __forceinline__ void split2h(float f0, float f1, uint32_t& hi, uint32_t& lo) {
    hi = packh2(f0, f1);
    float h0, h1;
    asm("{.reg .f16 a,b; mov.b32 {a,b}, %2; cvt.f32.f16 %0, a; cvt.f32.f16 %1, b;}"
        : "=f"(h0), "=f"(h1) : "r"(hi));
    lo = packh2(f0 - h0, f1 - h1);
}

__device__ __forceinline__ float ex2(float x) {
    float r;
    asm("ex2.approx.ftz.f32 %0, %1;" : "=f"(r) : "f"(x));
    return r;
}

__device__ __forceinline__ void ldm4(uint32_t* r, uint32_t addr) {
    asm volatile("ldmatrix.sync.aligned.m8n8.x4.shared.b16 {%0,%1,%2,%3}, [%4];"
                 : "=r"(r[0]), "=r"(r[1]), "=r"(r[2]), "=r"(r[3]) : "r"(addr));
}
__device__ __forceinline__ void ldm4t(uint32_t* r, uint32_t addr) {
    asm volatile("ldmatrix.sync.aligned.m8n8.x4.trans.shared.b16 {%0,%1,%2,%3}, [%4];"
                 : "=r"(r[0]), "=r"(r[1]), "=r"(r[2]), "=r"(r[3]) : "r"(addr));
}
__device__ __forceinline__ void mma16816(float* c, const uint32_t* a,
                                         uint32_t b0, uint32_t b1) {
    asm volatile("mma.sync.aligned.m16n8k16.row.col.f32.f16.f16.f32 "
                 "{%0,%1,%2,%3}, {%4,%5,%6,%7}, {%8,%9}, {%0,%1,%2,%3};"
                 : "+f"(c[0]), "+f"(c[1]), "+f"(c[2]), "+f"(c[3])
                 : "r"(a[0]), "r"(a[1]), "r"(a[2]), "r"(a[3]), "r"(b0), "r"(b1));
}

#define MBAR_INIT(a, n) asm volatile("mbarrier.init.shared.b64 [%0], %1;" :: "r"(a), "r"(n) : "memory")
#define MBAR_ARRIVE(a)  asm volatile("mbarrier.arrive.shared.b64 _, [%0];" :: "r"(a) : "memory")

#define MBAR_WAIT(a, par) do {                                                  \
    uint32_t _m = (a), _p = (par), _d;                                          \
    asm volatile("{\n\t.reg .pred p;\n\t"                                       \
        "mbarrier.try_wait.parity.acquire.cta.shared::cta.b64 p, [%1], %2;\n\t" \
        "selp.b32 %0, 1, 0, p;\n\t}" : "=r"(_d) : "r"(_m), "r"(_p) : "memory"); \
    if (!_d) {                                                                  \
        asm volatile("{\n\t.reg .pred P1;\n\t"                                  \
        "WL_%=:\n\t"                                                            \
        "mbarrier.try_wait.parity.acquire.cta.shared::cta.b64 P1, [%0], %1, 0x989680;\n\t" \
        "@P1 bra.uni WD_%=;\n\t"                                                \
        "bra.uni WL_%=;\n\t"                                                    \
        "WD_%=:\n\t}" :: "r"(_m), "r"(_p) : "memory");                          \
    }                                                                           \
} while (0)

__global__ __launch_bounds__(384, 1)
void fa_ws_kernel(const float* __restrict__ gq,
                  const float* __restrict__ gk,
                  const float* __restrict__ gv,
                  float* __restrict__ gout,
                  int seqlen)
{
    extern __shared__ char smem[];
    const uint32_t sb = smem_u32(smem);
    const int tid = threadIdx.x;
    const int lane = tid & 31;
    const int w = tid >> 5;                         // warps 0-7 consume, 8-11 produce
    const int bh = blockIdx.y;
    const int qtile = gridDim.x - 1 - blockIdx.x;   // heavy tiles first
    const int qbase = qtile * BT;
    const size_t bh_off = (size_t)bh * seqlen * HD;
    const int NC = 2 * qtile + 2;                   // 64-row kv chunks

    if (tid == 0) {
        #pragma unroll
        for (int s = 0; s < NSTG; ++s) {
            MBAR_INIT(sb + s * 8, 128);        // full: 4 producer warps arrive
            MBAR_INIT(sb + 32 + s * 8, 256);   // empty: 8 consumer warps arrive
        }
    }

    // ---- Q tile -> smem fp16 hi/lo, scale*log2e folded (consumer threads) ----
    if (tid < 256) {
        const float* qp = gq + bh_off + (size_t)qbase * HD;
        #pragma unroll
        for (int it = 0; it < 16; ++it) {
            int idx = tid + it * 256;
            int r = idx >> 5, c4 = idx & 31;
            float4 t = *(const float4*)(qp + (size_t)r * HD + c4 * 4);
            uint32_t h01, l01, h23, l23;
            split2h(t.x * SCALE_L2E, t.y * SCALE_L2E, h01, l01);
            split2h(t.z * SCALE_L2E, t.w * SCALE_L2E, h23, l23);
            uint32_t off = (uint32_t)(r * ROWB + c4 * 8);
            *(uint2*)(smem + SQHI + off) = make_uint2(h01, h23);
            *(uint2*)(smem + SQLO + off) = make_uint2(l01, l23);
        }
    }
    __syncthreads();   // barriers initialized + Q resident

    if (w >= 8) {
        // ================= PRODUCER (4 warps, 128 threads) =================
        const int ptid = tid - 256;     // 0..127
        for (int jc = 0; jc < NC; ++jc) {
            const int s = jc & 3;
            if (jc >= NSTG)
                MBAR_WAIT(sb + 32 + s * 8, ((jc - NSTG) >> 2) & 1);
            const uint32_t stg = (uint32_t)(STG0 + s * STAGE_B);
            const float* kp = gk + bh_off + (size_t)(jc * BC) * HD;
            const float* vp = gv + bh_off + (size_t)(jc * BC) * HD;
            #pragma unroll 4
            for (int it = 0; it < 16; ++it) {
                int idx = ptid + it * 128;          // 0..2047 float4 units
                int r = idx >> 5, c4 = idx & 31;
                uint32_t off = stg + (uint32_t)(r * ROWB + c4 * 8);
                float4 tk = *(const float4*)(kp + (size_t)r * HD + c4 * 4);
                *(uint2*)(smem + off + OFF_K) =
                    make_uint2(packh2(tk.x, tk.y), packh2(tk.z, tk.w));
                float4 tv = *(const float4*)(vp + (size_t)r * HD + c4 * 4);
                *(uint2*)(smem + off + OFF_V) =
                    make_uint2(packh2(tv.x, tv.y), packh2(tv.z, tv.w));
            }
            MBAR_ARRIVE(sb + s * 8);
        }
        return;
    }

    // ================= CONSUMER (8 warps, 256 threads) =================
    const int rl0 = 16 * w + (lane >> 2);               // local row (low half)
    const uint32_t coladd = (lane & 16) ? 16u : 0u;     // +8 elems = 16 B
    const uint32_t arow_off = (uint32_t)((16 * w + (lane & 15)) * ROWB) + coladd;
    const uint32_t brow_off = (uint32_t)((lane & 15) * ROWB) + coladd;
    const int gr0 = qbase + rl0, gr1 = gr0 + 8;

    float m0 = -1e30f, m1 = -1e30f, l0 = 0.0f, l1 = 0.0f;  // l kept per-lane
    float oa[16][4];
    #pragma unroll
    for (int t = 0; t < 16; ++t)
        #pragma unroll
        for (int e = 0; e < 4; ++e) oa[t][e] = 0.0f;

    for (int jc = 0; jc < NC; ++jc) {
        const int s = jc & 3;
        MBAR_WAIT(sb + s * 8, (jc >> 2) & 1);
        const uint32_t stg = sb + (uint32_t)(STG0 + s * STAGE_B);

        // ---- S = (Qhi + Qlo) @ Khi^T over 64 kv cols (2 MMA terms) ----
        float sa[8][4];
        #pragma unroll
        for (int t = 0; t < 8; ++t)
            #pragma unroll
            for (int e = 0; e < 4; ++e) sa[t][e] = 0.0f;

        #pragma unroll 2
        for (int s8 = 0; s8 < 8; ++s8) {        // k16 over d
            uint32_t ah[4], al[4];
            ldm4(ah, sb + SQHI + arow_off + s8 * 32);
            ldm4(al, sb + SQLO + arow_off + s8 * 32);
            uint32_t bhh[4][4];
            #pragma unroll
            for (int t2 = 0; t2 < 4; ++t2) {
                uint32_t baddr = stg + OFF_K + (uint32_t)(t2 * 16 * ROWB) + brow_off + s8 * 32;
                ldm4(bhh[t2], baddr);
            }
            #pragma unroll
            for (int t2 = 0; t2 < 4; ++t2) {
                mma16816(sa[2 * t2],     ah, bhh[t2][0], bhh[t2][2]);
                mma16816(sa[2 * t2 + 1], ah, bhh[t2][1], bhh[t2][3]);
            }
            #pragma unroll
            for (int t2 = 0; t2 < 4; ++t2) {
                mma16816(sa[2 * t2],     al, bhh[t2][0], bhh[t2][2]);
                mma16816(sa[2 * t2 + 1], al, bhh[t2][1], bhh[t2][3]);
            }
        }

        // ---- causal mask (only the last two chunks touch the diagonal) ----
        if (jc >= 2 * qtile) {
            const int colbase = jc * BC + 2 * (lane & 3);
            #pragma unroll
            for (int t = 0; t < 8; ++t) {
                int c = colbase + 8 * t;
                if (c     > gr0) sa[t][0] = -1e30f;
                if (c + 1 > gr0) sa[t][1] = -1e30f;
                if (c     > gr1) sa[t][2] = -1e30f;
                if (c + 1 > gr1) sa[t][3] = -1e30f;
            }
        }

        // ---- row max, reduce over 4 lanes ----
        float mx0 = -1e30f, mx1 = -1e30f;
        #pragma unroll
        for (int t = 0; t < 8; ++t) {
            mx0 = fmaxf(mx0, fmaxf(sa[t][0], sa[t][1]));
            mx1 = fmaxf(mx1, fmaxf(sa[t][2], sa[t][3]));
        }
        mx0 = fmaxf(mx0, __shfl_xor_sync(0xffffffffu, mx0, 1));
        mx0 = fmaxf(mx0, __shfl_xor_sync(0xffffffffu, mx0, 2));
        mx1 = fmaxf(mx1, __shfl_xor_sync(0xffffffffu, mx1, 1));
        mx1 = fmaxf(mx1, __shfl_xor_sync(0xffffffffu, mx1, 2));

        float mn0 = fmaxf(m0, mx0), mn1 = fmaxf(m1, mx1);
        // skip the O/l rescale entirely when no lane's running max moved
        bool moved = (mn0 != m0) || (mn1 != m1);
        if (__any_sync(0xffffffffu, moved)) {
            float f0 = ex2(m0 - mn0), f1 = ex2(m1 - mn1);
            m0 = mn0; m1 = mn1;
            l0 *= f0; l1 *= f1;
            #pragma unroll
            for (int t = 0; t < 16; ++t) {
                oa[t][0] *= f0; oa[t][1] *= f0;
                oa[t][2] *= f1; oa[t][3] *= f1;
            }
        }

        // ---- per-sub-block: exp (ex2) then PV MMAs (1 term), interleaved ----
        #pragma unroll
        for (int s4 = 0; s4 < 4; ++s4) {        // k16 over kv
            #pragma unroll
            for (int h = 0; h < 2; ++h) {
                int t = 2 * s4 + h;
                sa[t][0] = ex2(sa[t][0] - mn0);
                sa[t][1] = ex2(sa[t][1] - mn0);
                sa[t][2] = ex2(sa[t][2] - mn1);
                sa[t][3] = ex2(sa[t][3] - mn1);
                l0 += sa[t][0] + sa[t][1];
                l1 += sa[t][2] + sa[t][3];
            }
            uint32_t ph[4];
            ph[0] = packh2(sa[2 * s4][0],     sa[2 * s4][1]);
            ph[1] = packh2(sa[2 * s4][2],     sa[2 * s4][3]);
            ph[2] = packh2(sa[2 * s4 + 1][0], sa[2 * s4 + 1][1]);
            ph[3] = packh2(sa[2 * s4 + 1][2], sa[2 * s4 + 1][3]);
            uint32_t vrow = stg + OFF_V + (uint32_t)((16 * s4 + (lane & 15)) * ROWB) + coladd;
            #pragma unroll
            for (int half = 0; half < 2; ++half) {
                uint32_t vhh[4][4];
                #pragma unroll
                for (int q4 = 0; q4 < 4; ++q4)
                    ldm4t(vhh[q4], vrow + (half * 4 + q4) * 32);
                #pragma unroll
                for (int q4 = 0; q4 < 4; ++q4) {
                    int t2 = half * 4 + q4;
                    mma16816(oa[2 * t2],     ph, vhh[q4][0], vhh[q4][1]);
                    mma16816(oa[2 * t2 + 1], ph, vhh[q4][2], vhh[q4][3]);
                }
            }
        }

        MBAR_ARRIVE(sb + 32 + s * 8);
    }

    // ---- epilogue: reduce l across the 4 lanes, O /= l, write out ----
    {
        l0 += __shfl_xor_sync(0xffffffffu, l0, 1);
        l0 += __shfl_xor_sync(0xffffffffu, l0, 2);
        l1 += __shfl_xor_sync(0xffffffffu, l1, 1);
        l1 += __shfl_xor_sync(0xffffffffu, l1, 2);
        float i0 = 1.0f / l0, i1 = 1.0f / l1;
        float* o0 = gout + bh_off + (size_t)(qbase + rl0) * HD;
        float* o1 = o0 + 8 * HD;
        #pragma unroll
        for (int t = 0; t < 16; ++t) {
            int c = 8 * t + 2 * (lane & 3);
            *(float2*)(o0 + c) = make_float2(oa[t][0] * i0, oa[t][1] * i0);
            *(float2*)(o1 + c) = make_float2(oa[t][2] * i1, oa[t][3] * i1);
        }
    }
}

extern "C" void kernel_launch(void* const* d_in, const int* in_sizes, int n_in,
                              void* d_out, int out_size)
{
    const float* q = (const float*)d_in[0];
    const float* k = (const float*)d_in[1];
    const float* v = (const float*)d_in[2];
    float* out = (float*)d_out;

    const int seqlen = 2048;
    const int nbh = in_sizes[0] / (seqlen * HD);   // B*H = 32

    cudaFuncSetAttribute(fa_ws_kernel,
                         cudaFuncAttributeMaxDynamicSharedMemorySize, SM_TOTAL);

    dim3 grid(seqlen / BT, nbh);
    fa_ws_kernel<<<grid, 384, SM_TOTAL>>>(q, k, v, out, seqlen);
}

// round 15
// speedup vs baseline: 1.3006x; 1.3006x over previous
#include <cuda_runtime.h>
#include <cuda_fp16.h>
#include <cstdint>

// Causal FlashAttention via fp16 mma.sync with asymmetric split (sm_103).
// S = (Qhi+Qlo)*Khi (exact-Q x fp16-K, 2 terms — protects the exponent),
// O = Phi*Vhi       (fp16-P x fp16-V, 1 term — P enters linearly, err ~3e-4).
// Warp-specialized: 8 consumer + 4 producer warps, 4-stage mbarrier ring.
// R14 = R12 structure exactly, with PV reduced to one term as a single
// 16-load -> 16-MMA block (same register footprint/ILP as R12's PV).

#define HD 128
#define BT 128                     // q rows per CTA
#define BC 64                      // kv rows per chunk
#define STR 136                    // smem row stride in fp16 elems (272 B)
#define ROWB (STR * 2)             // 272 bytes per row
#define QTILE_B (BT * ROWB)        // 34816 B
#define CTILE_B (BC * ROWB)        // 17408 B per tile buffer
#define NSTG 4
#define SCALE_L2E 0.12753102331595943f  // (1/sqrt(128)) * log2(e)

// smem map (bytes): full[s]=s*8, empty[s]=32+s*8
#define SQHI 1024
#define SQLO (SQHI + QTILE_B)
#define STG0 (SQLO + QTILE_B)          // stage s at STG0 + s*STAGE_B
#define STAGE_B (2 * CTILE_B)          // K, V (hi only)
#define OFF_K 0
#define OFF_V CTILE_B
#define SM_TOTAL (STG0 + NSTG * STAGE_B)  // 209920 B

__device__ __forceinline__ uint32_t smem_u32(const void* p) {
    uint32_t a;
    asm("{ .reg .u64 t; cvta.to.shared.u64 t, %1; cvt.u32.u64 %0, t; }" : "=r"(a) : "l"(p));
    return a;
}

// pack two f32 -> f16x2 (lo = f0, hi = f1)
__device__ __forceinline__ uint32_t packh2(float f0, float f1) {
    uint32_t r;
    asm("cvt.rn.f16x2.f32 %0, %1, %2;" : "=r"(r) : "f"(f1), "f"(f0));
    return r;
}
// split two floats into fp16x2 hi + fp16x2 lo (lo = rounded residual)
__device__ __forceinline__ void split2h(float f0, float f1, uint32_t& hi, uint32_t& lo) {
    hi = packh2(f0, f1);
    float h0, h1;
    asm("{.reg .f16 a,b; mov.b32 {a,b}, %2; cvt.f32.f16 %0, a; cvt.f32.f16 %1, b;}"
        : "=f"(h0), "=f"(h1) : "r"(hi));
    lo = packh2(f0 - h0, f1 - h1);
}

__device__ __forceinline__ float ex2(float x) {
    float r;
    asm("ex2.approx.ftz.f32 %0, %1;" : "=f"(r) : "f"(x));
    return r;
}

__device__ __forceinline__ void ldm4(uint32_t* r, uint32_t addr) {
    asm volatile("ldmatrix.sync.aligned.m8n8.x4.shared.b16 {%0,%1,%2,%3}, [%4];"
                 : "=r"(r[0]), "=r"(r[1]), "=r"(r[2]), "=r"(r[3]) : "r"(addr));
}
__device__ __forceinline__ void ldm4t(uint32_t* r, uint32_t addr) {
    asm volatile("ldmatrix.sync.aligned.m8n8.x4.trans.shared.b16 {%0,%1,%2,%3}, [%4];"
                 : "=r"(r[0]), "=r"(r[1]), "=r"(r[2]), "=r"(r[3]) : "r"(addr));
}
__device__ __forceinline__ void mma16816(float* c, const uint32_t* a,
                                         uint32_t b0, uint32_t b1) {
    asm volatile("mma.sync.aligned.m16n8k16.row.col.f32.f16.f16.f32 "
                 "{%0,%1,%2,%3}, {%4,%5,%6,%7}, {%8,%9}, {%0,%1,%2,%3};"
                 : "+f"(c[0]), "+f"(c[1]), "+f"(c[2]), "+f"(c[3])
                 : "r"(a[0]), "r"(a[1]), "r"(a[2]), "r"(a[3]), "r"(b0), "r"(b1));
}

#define MBAR_INIT(a, n) asm volatile("mbarrier.init.shared.b64 [%0], %1;" :: "r"(a), "r"(n) : "memory")
#define MBAR_ARRIVE(a)  asm volatile("mbarrier.arrive.shared.b64 _, [%0];" :: "r"(a) : "memory")

#define MBAR_WAIT(a, par) do {                                                  \
    uint32_t _m = (a), _p = (par), _d;                                          \
    asm volatile("{\n\t.reg .pred p;\n\t"                                       \
        "mbarrier.try_wait.parity.acquire.cta.shared::cta.b64 p, [%1], %2;\n\t" \
        "selp.b32 %0, 1, 0, p;\n\t}" : "=r"(_d) : "r"(_m), "r"(_p) : "memory"); \
    if (!_d) {                                                                  \
        asm volatile("{\n\t.reg .pred P1;\n\t"                                  \
        "WL_%=:\n\t"                                                            \
        "mbarrier.try_wait.parity.acquire.cta.shared::cta.b64 P1, [%0], %1, 0x989680;\n\t" \
        "@P1 bra.uni WD_%=;\n\t"                                                \
        "bra.uni WL_%=;\n\t"                                                    \
        "WD_%=:\n\t}" :: "r"(_m), "r"(_p) : "memory");                          \
    }                                                                           \
} while (0)

__global__ __launch_bounds__(384, 1)
void fa_ws_kernel(const float* __restrict__ gq,
                  const float* __restrict__ gk,
                  const float* __restrict__ gv,
                  float* __restrict__ gout,
                  int seqlen)
{
    extern __shared__ char smem[];
    const uint32_t sb = smem_u32(smem);
    const int tid = threadIdx.x;
    const int lane = tid & 31;
    const int w = tid >> 5;                         // warps 0-7 consume, 8-11 produce
    const int bh = blockIdx.y;
    const int qtile = gridDim.x - 1 - blockIdx.x;   // heavy tiles first
    const int qbase = qtile * BT;
    const size_t bh_off = (size_t)bh * seqlen * HD;
    const int NC = 2 * qtile + 2;                   // 64-row kv chunks

    if (tid == 0) {
        #pragma unroll
        for (int s = 0; s < NSTG; ++s) {
            MBAR_INIT(sb + s * 8, 128);        // full: 4 producer warps arrive
            MBAR_INIT(sb + 32 + s * 8, 256);   // empty: 8 consumer warps arrive
        }
    }

    // ---- Q tile -> smem fp16 hi/lo, scale*log2e folded (consumer threads) ----
    if (tid < 256) {
        const float* qp = gq + bh_off + (size_t)qbase * HD;
        #pragma unroll
        for (int it = 0; it < 16; ++it) {
            int idx = tid + it * 256;
            int r = idx >> 5, c4 = idx & 31;
            float4 t = *(const float4*)(qp + (size_t)r * HD + c4 * 4);
            uint32_t h01, l01, h23, l23;
            split2h(t.x * SCALE_L2E, t.y * SCALE_L2E, h01, l01);
            split2h(t.z * SCALE_L2E, t.w * SCALE_L2E, h23, l23);
            uint32_t off = (uint32_t)(r * ROWB + c4 * 8);
            *(uint2*)(smem + SQHI + off) = make_uint2(h01, h23);
            *(uint2*)(smem + SQLO + off) = make_uint2(l01, l23);
        }
    }
    __syncthreads();   // barriers initialized + Q resident

    if (w >= 8) {
        // ================= PRODUCER (4 warps, 128 threads) =================
        const int ptid = tid - 256;     // 0..127
        for (int jc = 0; jc < NC; ++jc) {
            const int s = jc & 3;
            if (jc >= NSTG)
                MBAR_WAIT(sb + 32 + s * 8, ((jc - NSTG) >> 2) & 1);
            const uint32_t stg = (uint32_t)(STG0 + s * STAGE_B);
            const float* kp = gk + bh_off + (size_t)(jc * BC) * HD;
            const float* vp = gv + bh_off + (size_t)(jc * BC) * HD;
            #pragma unroll 4
            for (int it = 0; it < 16; ++it) {
                int idx = ptid + it * 128;          // 0..2047 float4 units
                int r = idx >> 5, c4 = idx & 31;
                uint32_t off = stg + (uint32_t)(r * ROWB + c4 * 8);
                float4 tk = *(const float4*)(kp + (size_t)r * HD + c4 * 4);
                *(uint2*)(smem + off + OFF_K) =
                    make_uint2(packh2(tk.x, tk.y), packh2(tk.z, tk.w));
                float4 tv = *(const float4*)(vp + (size_t)r * HD + c4 * 4);
                *(uint2*)(smem + off + OFF_V) =
                    make_uint2(packh2(tv.x, tv.y), packh2(tv.z, tv.w));
            }
            MBAR_ARRIVE(sb + s * 8);
        }
        return;
    }

    // ================= CONSUMER (8 warps, 256 threads) =================
    const int rl0 = 16 * w + (lane >> 2);               // local row (low half)
    const uint32_t coladd = (lane & 16) ? 16u : 0u;     // +8 elems = 16 B
    const uint32_t arow_off = (uint32_t)((16 * w + (lane & 15)) * ROWB) + coladd;
    const uint32_t brow_off = (uint32_t)((lane & 15) * ROWB) + coladd;
    const int gr0 = qbase + rl0, gr1 = gr0 + 8;

    float m0 = -1e30f, m1 = -1e30f, l0 = 0.0f, l1 = 0.0f;  // l kept per-lane
    float oa[16][4];
    #pragma unroll
    for (int t = 0; t < 16; ++t)
        #pragma unroll
        for (int e = 0; e < 4; ++e) oa[t][e] = 0.0f;

    for (int jc = 0; jc < NC; ++jc) {
        const int s = jc & 3;
        MBAR_WAIT(sb + s * 8, (jc >> 2) & 1);
        const uint32_t stg = sb + (uint32_t)(STG0 + s * STAGE_B);

        // ---- S = (Qhi + Qlo) @ Khi^T over 64 kv cols (2 MMA terms) ----
        float sa[8][4];
        #pragma unroll
        for (int t = 0; t < 8; ++t)
            #pragma unroll
            for (int e = 0; e < 4; ++e) sa[t][e] = 0.0f;

        #pragma unroll 2
        for (int s8 = 0; s8 < 8; ++s8) {        // k16 over d
            uint32_t ah[4], al[4];
            ldm4(ah, sb + SQHI + arow_off + s8 * 32);
            ldm4(al, sb + SQLO + arow_off + s8 * 32);
            uint32_t bhh[4][4];
            #pragma unroll
            for (int t2 = 0; t2 < 4; ++t2) {
                uint32_t baddr = stg + OFF_K + (uint32_t)(t2 * 16 * ROWB) + brow_off + s8 * 32;
                ldm4(bhh[t2], baddr);
            }
            #pragma unroll
            for (int t2 = 0; t2 < 4; ++t2) {
                mma16816(sa[2 * t2],     ah, bhh[t2][0], bhh[t2][2]);
                mma16816(sa[2 * t2 + 1], ah, bhh[t2][1], bhh[t2][3]);
            }
            #pragma unroll
            for (int t2 = 0; t2 < 4; ++t2) {
                mma16816(sa[2 * t2],     al, bhh[t2][0], bhh[t2][2]);
                mma16816(sa[2 * t2 + 1], al, bhh[t2][1], bhh[t2][3]);
            }
        }

        // ---- causal mask (only the last two chunks touch the diagonal) ----
        if (jc >= 2 * qtile) {
            const int colbase = jc * BC + 2 * (lane & 3);
            #pragma unroll
            for (int t = 0; t < 8; ++t) {
                int c = colbase + 8 * t;
                if (c     > gr0) sa[t][0] = -1e30f;
                if (c + 1 > gr0) sa[t][1] = -1e30f;
                if (c     > gr1) sa[t][2] = -1e30f;
                if (c + 1 > gr1) sa[t][3] = -1e30f;
            }
        }

        // ---- row max, reduce over 4 lanes ----
        float mx0 = -1e30f, mx1 = -1e30f;
        #pragma unroll
        for (int t = 0; t < 8; ++t) {
            mx0 = fmaxf(mx0, fmaxf(sa[t][0], sa[t][1]));
            mx1 = fmaxf(mx1, fmaxf(sa[t][2], sa[t][3]));
        }
        mx0 = fmaxf(mx0, __shfl_xor_sync(0xffffffffu, mx0, 1));
        mx0 = fmaxf(mx0, __shfl_xor_sync(0xffffffffu, mx0, 2));
        mx1 = fmaxf(mx1, __shfl_xor_sync(0xffffffffu, mx1, 1));
        mx1 = fmaxf(mx1, __shfl_xor_sync(0xffffffffu, mx1, 2));

        float mn0 = fmaxf(m0, mx0), mn1 = fmaxf(m1, mx1);
        float f0 = ex2(m0 - mn0), f1 = ex2(m1 - mn1);
        m0 = mn0; m1 = mn1;
        l0 *= f0; l1 *= f1;

        #pragma unroll
        for (int t = 0; t < 16; ++t) {
            oa[t][0] *= f0; oa[t][1] *= f0;
            oa[t][2] *= f1; oa[t][3] *= f1;
        }

        // ---- per-sub-block: exp (ex2) then PV MMAs (1 term), interleaved ----
        #pragma unroll
        for (int s4 = 0; s4 < 4; ++s4) {        // k16 over kv
            #pragma unroll
            for (int h = 0; h < 2; ++h) {
                int t = 2 * s4 + h;
                sa[t][0] = ex2(sa[t][0] - mn0);
                sa[t][1] = ex2(sa[t][1] - mn0);
                sa[t][2] = ex2(sa[t][2] - mn1);
                sa[t][3] = ex2(sa[t][3] - mn1);
                l0 += sa[t][0] + sa[t][1];
                l1 += sa[t][2] + sa[t][3];
            }
            uint32_t ph[4];
            ph[0] = packh2(sa[2 * s4][0],     sa[2 * s4][1]);
            ph[1] = packh2(sa[2 * s4][2],     sa[2 * s4][3]);
            ph[2] = packh2(sa[2 * s4 + 1][0], sa[2 * s4 + 1][1]);
            ph[3] = packh2(sa[2 * s4 + 1][2], sa[2 * s4 + 1][3]);
            uint32_t vrow = stg + OFF_V + (uint32_t)((16 * s4 + (lane & 15)) * ROWB) + coladd;
            // single 16-load -> 16-MMA block (same depth/regs as R12's PV)
            uint32_t vhh[8][4];
            #pragma unroll
            for (int q8 = 0; q8 < 8; ++q8)
                ldm4t(vhh[q8], vrow + q8 * 32);
            #pragma unroll
            for (int q8 = 0; q8 < 8; ++q8) {
                mma16816(oa[2 * q8],     ph, vhh[q8][0], vhh[q8][1]);
                mma16816(oa[2 * q8 + 1], ph, vhh[q8][2], vhh[q8][3]);
            }
        }

        MBAR_ARRIVE(sb + 32 + s * 8);
    }

    // ---- epilogue: reduce l across the 4 lanes, O /= l, write out ----
    {
        l0 += __shfl_xor_sync(0xffffffffu, l0, 1);
        l0 += __shfl_xor_sync(0xffffffffu, l0, 2);
        l1 += __shfl_xor_sync(0xffffffffu, l1, 1);
        l1 += __shfl_xor_sync(0xffffffffu, l1, 2);
        float i0 = 1.0f / l0, i1 = 1.0f / l1;
        float* o0 = gout + bh_off + (size_t)(qbase + rl0) * HD;
        float* o1 = o0 + 8 * HD;
        #pragma unroll
        for (int t = 0; t < 16; ++t) {
            int c = 8 * t + 2 * (lane & 3);
            *(float2*)(o0 + c) = make_float2(oa[t][0] * i0, oa[t][1] * i0);
            *(float2*)(o1 + c) = make_float2(oa[t][2] * i1, oa[t][3] * i1);
        }
    }
}

extern "C" void kernel_launch(void* const* d_in, const int* in_sizes, int n_in,
                              void* d_out, int out_size)
{
    const float* q = (const float*)d_in[0];
    const float* k = (const float*)d_in[1];
    const float* v = (const float*)d_in[2];
    float* out = (float*)d_out;

    const int seqlen = 2048;
    const int nbh = in_sizes[0] / (seqlen * HD);   // B*H = 32

    cudaFuncSetAttribute(fa_ws_kernel,
                         cudaFuncAttributeMaxDynamicSharedMemorySize, SM_TOTAL);

    dim3 grid(seqlen / BT, nbh);
    fa_ws_kernel<<<grid, 384, SM_TOTAL>>>(q, k, v, out, seqlen);
}